// round 1
// baseline (speedup 1.0000x reference)
#include <cuda_runtime.h>
#include <math.h>

#define BB      32
#define TSEQ    512
#define EPROJ   512
#define DUN     1024
#define ODIMC   10000
#define ATTD    320
#define LLEN    128
#define LP1     129
#define SOSEOS  9999
#define NROWS   (BB*LP1)   // 4128

typedef unsigned long long ull;

__device__ __forceinline__ ull pack2(float x){ ull r; asm("mov.b64 %0, {%1, %1};":"=l"(r):"f"(x)); return r; }
__device__ __forceinline__ void fma2(ull &a, ull x, ull y){ asm("fma.rn.f32x2 %0, %1, %2, %3;":"=l"(a):"l"(x),"l"(y),"l"(a)); }
__device__ __forceinline__ float2 unpack2(ull v){ float2 f; asm("mov.b64 {%0, %1}, %2;":"=f"(f.x),"=f"(f.y):"l"(v)); return f; }
__device__ __forceinline__ float sigmoidf_(float x){ return 1.0f/(1.0f+expf(-x)); }

// ---------------- scratch (device globals: no allocation allowed) ----------------
__device__ float g_pre_enc[BB*TSEQ*ATTD];          // [b][t][a]  21 MB
__device__ float g_attc[BB*EPROJ];
__device__ float g_z0[BB*DUN], g_c0[BB*DUN], g_z1[BB*DUN], g_c1[BB*DUN];
__device__ float g_part[2*BB*4096];                // k-split partial gates [s][b][n]
__device__ float g_zs[BB*LP1*DUN];                 // [b][l][j] 16.9 MB
__device__ float g_logits[(size_t)NROWS*ODIMC];    // 165 MB
__device__ float g_rownll[NROWS];
__device__ int   g_rowhit[NROWS];

// ---------------- init recurrent state ----------------
__global__ void init_state(float* z0,float* c0,float* z1,float* c1){
    int i = blockIdx.x*blockDim.x + threadIdx.x;
    if (i < BB*DUN){ z0[i]=0.f; c0[i]=0.f; z1[i]=0.f; c1[i]=0.f; }
}

// ---------------- generic C[M,N] = act(A[M,K] @ W[N,K]^T + bias) ----------------
// BM=BN=64, BK=16, 256 threads, 4x4 thread tile, f32x2 FMAs.
__global__ void sgemm_nt(const float* __restrict__ A, const float* __restrict__ W,
                         const float* __restrict__ bias, float* __restrict__ C,
                         int M, int N, int K, int act)
{
    __shared__ __align__(16) float As[16][68];
    __shared__ __align__(16) float Ws[16][68];
    int bm = blockIdx.x * 64, bn = blockIdx.y * 64;
    int tx = threadIdx.x & 15, ty = threadIdx.x >> 4;
    ull acc[4][2] = {{0ull,0ull},{0ull,0ull},{0ull,0ull},{0ull,0ull}};
    for (int k0 = 0; k0 < K; k0 += 16){
        #pragma unroll
        for (int j=0;j<4;j++){
            int i = threadIdx.x + j*256;
            int m = i >> 4, k = i & 15;
            int gm = bm + m;
            As[k][m] = (gm < M) ? A[(size_t)gm*K + k0 + k] : 0.f;
            int gn = bn + m;
            Ws[k][m] = (gn < N) ? W[(size_t)gn*K + k0 + k] : 0.f;
        }
        __syncthreads();
        #pragma unroll
        for (int k=0;k<16;k++){
            float4 a4 = *(const float4*)&As[k][ty*4];
            ulonglong2 w2 = *(const ulonglong2*)&Ws[k][tx*4];
            ull a;
            a = pack2(a4.x); fma2(acc[0][0],a,w2.x); fma2(acc[0][1],a,w2.y);
            a = pack2(a4.y); fma2(acc[1][0],a,w2.x); fma2(acc[1][1],a,w2.y);
            a = pack2(a4.z); fma2(acc[2][0],a,w2.x); fma2(acc[2][1],a,w2.y);
            a = pack2(a4.w); fma2(acc[3][0],a,w2.x); fma2(acc[3][1],a,w2.y);
        }
        __syncthreads();
    }
    #pragma unroll
    for (int i=0;i<4;i++){
        int m = bm + ty*4 + i;
        if (m >= M) continue;
        #pragma unroll
        for (int jp=0;jp<2;jp++){
            float2 v = unpack2(acc[i][jp]);
            int n = bn + tx*4 + jp*2;
            if (n < N){   float r = v.x + (bias?bias[n]:0.f);   if(act) r=tanhf(r); C[(size_t)m*N+n]   = r; }
            if (n+1 < N){ float r = v.y + (bias?bias[n+1]:0.f); if(act) r=tanhf(r); C[(size_t)m*N+n+1] = r; }
        }
    }
}

// ---------------- fused dec + attention (one block per batch element) ----------------
__global__ void attn_kernel(const float* __restrict__ hs, const int* __restrict__ hlens,
                            const float* __restrict__ pre_enc, const float* __restrict__ Wdec,
                            const float* __restrict__ z0, float* __restrict__ attc)
{
    int b = blockIdx.x;
    int tid = threadIdx.x;
    int warp = tid >> 5, lane = tid & 31;
    __shared__ __align__(16) float z_s[DUN];
    __shared__ __align__(16) float dec_s[ATTD];
    __shared__ float sc_s[TSEQ];
    __shared__ float red_s[34];
    int hlen = hlens[b];

    for (int i=tid;i<DUN;i+=256) z_s[i] = z0[b*DUN + i];
    __syncthreads();

    // dec[a] = tanh(z0[b] . Wdec[a])
    for (int a = warp; a < ATTD; a += 8){
        const float* wr = Wdec + (size_t)a*DUN;
        ull acc = 0ull;
        #pragma unroll 4
        for (int k = lane*2; k < DUN; k += 64)
            fma2(acc, *(const ull*)(wr + k), *(const ull*)(z_s + k));
        float2 p = unpack2(acc);
        float v = p.x + p.y;
        #pragma unroll
        for (int o=16;o;o>>=1) v += __shfl_xor_sync(0xffffffffu, v, o);
        if (lane==0) dec_s[a] = tanhf(v);
    }
    __syncthreads();

    // scores
    for (int tt = tid; tt < TSEQ; tt += 256){
        const float* pr = pre_enc + ((size_t)b*TSEQ + tt)*ATTD;
        ull acc = 0ull;
        #pragma unroll 8
        for (int a=0;a<ATTD;a+=2)
            fma2(acc, *(const ull*)(pr+a), *(const ull*)(dec_s+a));
        float2 p = unpack2(acc);
        float e = p.x + p.y;
        sc_s[tt] = (tt < hlen) ? 2.0f*e : -INFINITY;
    }
    __syncthreads();

    // max
    float lm = fmaxf(sc_s[tid], sc_s[tid+256]);
    #pragma unroll
    for (int o=16;o;o>>=1) lm = fmaxf(lm, __shfl_xor_sync(0xffffffffu, lm, o));
    if (lane==0) red_s[warp] = lm;
    __syncthreads();
    if (tid==0){ float mm=red_s[0]; for (int w=1;w<8;w++) mm=fmaxf(mm,red_s[w]); red_s[32]=mm; }
    __syncthreads();
    float vmax = red_s[32];

    // exp + sum
    float ps = 0.f;
    for (int tt=tid; tt<TSEQ; tt+=256){
        float p = (tt < hlen) ? expf(sc_s[tt] - vmax) : 0.f;
        sc_s[tt] = p; ps += p;
    }
    #pragma unroll
    for (int o=16;o;o>>=1) ps += __shfl_xor_sync(0xffffffffu, ps, o);
    if (lane==0) red_s[warp] = ps;
    __syncthreads();
    if (tid==0){ float s=0.f; for (int w=0;w<8;w++) s+=red_s[w]; red_s[33]=1.0f/s; }
    __syncthreads();
    float inv = red_s[33];

    // att_c[d] = sum_t w_t * hs[b][t][d]  (two d's per thread)
    const float* hb = hs + (size_t)b*TSEQ*EPROJ;
    int d = 2*tid;
    ull acc = 0ull;
    for (int t=0;t<hlen;t++){
        ull w2 = pack2(sc_s[t]);
        fma2(acc, w2, *(const ull*)(hb + (size_t)t*EPROJ + d));
    }
    float2 r = unpack2(acc);
    attc[b*EPROJ + d]     = r.x * inv;
    attc[b*EPROJ + d + 1] = r.y * inv;
}

// ---------------- LSTM gates GEMM: part[s][b][n] over half-K, gather-concat inputs ----------------
// BM=32(b), BN=64, BK=16, 128 threads, 4x4 tile, grid (64, 2 splits)
template<int LAYER>
__global__ void lstm_gates(const float* __restrict__ embed_w, const int* __restrict__ ys,
                           const float* __restrict__ attc, const float* __restrict__ z0,
                           const float* __restrict__ z1,
                           const float* __restrict__ Wih, const float* __restrict__ Whh,
                           float* __restrict__ part, int t, int Khalf)
{
    __shared__ __align__(16) float As[16][36];
    __shared__ __align__(16) float Ws[16][68];
    int s  = blockIdx.y;
    int bn = blockIdx.x * 64;
    int K0 = s * Khalf, K1 = K0 + Khalf;
    int tx = threadIdx.x & 15, ty = threadIdx.x >> 4;   // tx: n/4, ty: b/4
    ull acc[4][2] = {{0ull,0ull},{0ull,0ull},{0ull,0ull},{0ull,0ull}};
    for (int k0 = K0; k0 < K1; k0 += 16){
        #pragma unroll
        for (int j=0;j<4;j++){                 // A: 32x16
            int i = threadIdx.x + j*128;
            int m = i >> 4, k = (i & 15) + k0;
            float v;
            if (LAYER==0){
                if (k < DUN){ int tok = (t==0)?SOSEOS:ys[m*LLEN + (t-1)]; v = embed_w[(size_t)tok*DUN + k]; }
                else if (k < DUN+EPROJ) v = attc[m*EPROJ + (k-DUN)];
                else v = z0[m*DUN + (k-DUN-EPROJ)];
            } else {
                v = (k < DUN) ? z0[m*DUN + k] : z1[m*DUN + (k-DUN)];
            }
            As[i & 15][m] = v;
        }
        #pragma unroll
        for (int j=0;j<8;j++){                 // W: 64x16
            int i = threadIdx.x + j*128;
            int n = (i >> 4) + bn, k = (i & 15) + k0;
            float v;
            if (LAYER==0) v = (k < DUN+EPROJ) ? Wih[(size_t)n*(DUN+EPROJ) + k] : Whh[(size_t)n*DUN + (k-DUN-EPROJ)];
            else          v = (k < DUN)       ? Wih[(size_t)n*DUN + k]         : Whh[(size_t)n*DUN + (k-DUN)];
            Ws[i & 15][(i >> 4)] = v;
        }
        __syncthreads();
        #pragma unroll
        for (int k=0;k<16;k++){
            float4 a4 = *(const float4*)&As[k][ty*4];
            ulonglong2 w2 = *(const ulonglong2*)&Ws[k][tx*4];
            ull a;
            a = pack2(a4.x); fma2(acc[0][0],a,w2.x); fma2(acc[0][1],a,w2.y);
            a = pack2(a4.y); fma2(acc[1][0],a,w2.x); fma2(acc[1][1],a,w2.y);
            a = pack2(a4.z); fma2(acc[2][0],a,w2.x); fma2(acc[2][1],a,w2.y);
            a = pack2(a4.w); fma2(acc[3][0],a,w2.x); fma2(acc[3][1],a,w2.y);
        }
        __syncthreads();
    }
    float* dst = part + (size_t)s*BB*4096;
    #pragma unroll
    for (int i=0;i<4;i++){
        int m = ty*4 + i;
        #pragma unroll
        for (int jp=0;jp<2;jp++){
            float2 v = unpack2(acc[i][jp]);
            int n = bn + tx*4 + jp*2;
            dst[m*4096 + n]     = v.x;
            dst[m*4096 + n + 1] = v.y;
        }
    }
}

// ---------------- combine k-splits + biases + LSTM cell update ----------------
__global__ void lstm_cell(const float* __restrict__ part, const float* __restrict__ bih,
                          const float* __restrict__ bhh, float* __restrict__ z,
                          float* __restrict__ c, float* __restrict__ zs_out, int t)
{
    int idx = blockIdx.x*blockDim.x + threadIdx.x;
    if (idx >= BB*DUN) return;
    int b = idx >> 10, j = idx & 1023;
    const float* p0 = part + (size_t)b*4096;
    const float* p1 = part + (size_t)BB*4096 + (size_t)b*4096;
    float gi = p0[j]        + p1[j]        + bih[j]        + bhh[j];
    float gf = p0[1024 + j] + p1[1024 + j] + bih[1024 + j] + bhh[1024 + j];
    float gg = p0[2048 + j] + p1[2048 + j] + bih[2048 + j] + bhh[2048 + j];
    float go = p0[3072 + j] + p1[3072 + j] + bih[3072 + j] + bhh[3072 + j];
    float cn = sigmoidf_(gf) * c[idx] + sigmoidf_(gi) * tanhf(gg);
    float zn = sigmoidf_(go) * tanhf(cn);
    c[idx] = cn; z[idx] = zn;
    if (zs_out) zs_out[((size_t)b*LP1 + t)*DUN + j] = zn;
}

// ---------------- per-row logsumexp / argmax / nll ----------------
__global__ void rowloss(const float* __restrict__ logits, const int* __restrict__ ys,
                        float* __restrict__ rownll, int* __restrict__ rowhit)
{
    int r = blockIdx.x, tid = threadIdx.x;
    const float* row = logits + (size_t)r*ODIMC;
    __shared__ float sv[256]; __shared__ int si[256]; __shared__ double sd[256];
    float vmax = -INFINITY; int vidx = ODIMC;
    for (int i=tid;i<ODIMC;i+=256){ float v=row[i]; if (v>vmax){ vmax=v; vidx=i; } }
    sv[tid]=vmax; si[tid]=vidx; __syncthreads();
    for (int s=128;s;s>>=1){
        if (tid<s){
            float v2=sv[tid+s]; int i2=si[tid+s];
            if (v2>sv[tid] || (v2==sv[tid] && i2<si[tid])){ sv[tid]=v2; si[tid]=i2; }
        }
        __syncthreads();
    }
    float m = sv[0]; int amax = si[0];
    double ps = 0.0;
    for (int i=tid;i<ODIMC;i+=256) ps += (double)expf(row[i]-m);
    sd[tid]=ps; __syncthreads();
    for (int s=128;s;s>>=1){ if (tid<s) sd[tid]+=sd[tid+s]; __syncthreads(); }
    if (tid==0){
        int b = r / LP1, l = r % LP1;
        int tgt = (l < LLEN) ? ys[b*LLEN + l] : SOSEOS;
        double lse = (double)m + log(sd[0]);
        rownll[r] = (float)(lse - (double)row[tgt]);
        rowhit[r] = (amax == tgt) ? 1 : 0;
    }
}

// ---------------- final scalar reduction ----------------
__global__ void finalize(const float* __restrict__ rownll, const int* __restrict__ rowhit,
                         float* __restrict__ out, int out_size)
{
    __shared__ double sd[256]; __shared__ int sh[256];
    int tid = threadIdx.x;
    double s = 0.0; int h = 0;
    for (int i=tid;i<NROWS;i+=256){ s += (double)rownll[i]; h += rowhit[i]; }
    sd[tid]=s; sh[tid]=h; __syncthreads();
    for (int st=128;st;st>>=1){ if (tid<st){ sd[tid]+=sd[tid+st]; sh[tid]+=sh[tid+st]; } __syncthreads(); }
    if (tid==0){
        double loss = sd[0]/(double)NROWS * (double)LLEN;
        double acc  = (double)sh[0]/(double)NROWS;
        double ppl  = exp(loss/(double)BB);
        if (out_size>0) out[0]=(float)loss;
        if (out_size>1) out[1]=(float)acc;
        if (out_size>2) out[2]=(float)ppl;
    }
    for (int i=3+tid;i<out_size;i+=256) out[i]=0.f;
}

// ---------------- launcher ----------------
static void* symaddr(const void* sym){ void* p=nullptr; cudaGetSymbolAddress(&p, sym); return p; }

extern "C" void kernel_launch(void* const* d_in, const int* in_sizes, int n_in,
                              void* d_out, int out_size)
{
    const float* hs    = (const float*)d_in[0];
    const int*   hlens = (const int*)  d_in[1];
    const int*   ys    = (const int*)  d_in[2];
    const float* embed = (const float*)d_in[3];
    const float* Wenc  = (const float*)d_in[4];
    const float* benc  = (const float*)d_in[5];
    const float* Wdec  = (const float*)d_in[6];
    const float* Wih0  = (const float*)d_in[7];
    const float* Whh0  = (const float*)d_in[8];
    const float* bih0  = (const float*)d_in[9];
    const float* bhh0  = (const float*)d_in[10];
    const float* Wih1  = (const float*)d_in[11];
    const float* Whh1  = (const float*)d_in[12];
    const float* bih1  = (const float*)d_in[13];
    const float* bhh1  = (const float*)d_in[14];
    const float* Wout  = (const float*)d_in[15];
    const float* bout  = (const float*)d_in[16];
    float* out = (float*)d_out;

    float* pre_enc = (float*)symaddr(g_pre_enc);
    float* attc    = (float*)symaddr(g_attc);
    float* z0      = (float*)symaddr(g_z0);
    float* c0      = (float*)symaddr(g_c0);
    float* z1      = (float*)symaddr(g_z1);
    float* c1      = (float*)symaddr(g_c1);
    float* part    = (float*)symaddr(g_part);
    float* zs      = (float*)symaddr(g_zs);
    float* logits  = (float*)symaddr(g_logits);
    float* rownll  = (float*)symaddr(g_rownll);
    int*   rowhit  = (int*)  symaddr(g_rowhit);

    init_state<<<128,256>>>(z0,c0,z1,c1);

    // pre_enc = tanh(hs @ Wenc^T + benc):  [16384,320]
    sgemm_nt<<<dim3(256,5),256>>>(hs, Wenc, benc, pre_enc, BB*TSEQ, ATTD, EPROJ, 1);

    for (int t=0; t<LP1; t++){
        attn_kernel<<<BB,256>>>(hs, hlens, pre_enc, Wdec, z0, attc);
        lstm_gates<0><<<dim3(64,2),128>>>(embed, ys, attc, z0, z1, Wih0, Whh0, part, t, (DUN+EPROJ+DUN)/2);
        lstm_cell<<<128,256>>>(part, bih0, bhh0, z0, c0, (float*)nullptr, t);
        lstm_gates<1><<<dim3(64,2),128>>>(embed, ys, attc, z0, z1, Wih1, Whh1, part, t, (DUN+DUN)/2);
        lstm_cell<<<128,256>>>(part, bih1, bhh1, z1, c1, zs, t);
    }

    // logits = zs @ Wout^T + bout : [4128, 10000]
    sgemm_nt<<<dim3((NROWS+63)/64,(ODIMC+63)/64),256>>>(zs, Wout, bout, logits, NROWS, ODIMC, DUN, 0);

    rowloss<<<NROWS,256>>>(logits, ys, rownll, rowhit);
    finalize<<<1,256>>>(rownll, rowhit, out, out_size);
}

// round 2
// speedup vs baseline: 3.4612x; 3.4612x over previous
#include <cuda_runtime.h>
#include <math.h>

#define BB      32
#define TSEQ    512
#define EPROJ   512
#define DUN     1024
#define ODIMC   10000
#define ATTD    320
#define LLEN    128
#define LP1     129
#define SOSEOS  9999
#define NROWS   (BB*LP1)   // 4128
#define NSPLIT  16

typedef unsigned long long ull;

__device__ __forceinline__ ull pack2(float x){ ull r; asm("mov.b64 %0, {%1, %1};":"=l"(r):"f"(x)); return r; }
__device__ __forceinline__ void fma2(ull &a, ull x, ull y){ asm("fma.rn.f32x2 %0, %1, %2, %3;":"=l"(a):"l"(x),"l"(y),"l"(a)); }
__device__ __forceinline__ float2 unpack2(ull v){ float2 f; asm("mov.b64 {%0, %1}, %2;":"=f"(f.x),"=f"(f.y):"l"(v)); return f; }
__device__ __forceinline__ float sigmoidf_(float x){ return 1.0f/(1.0f+expf(-x)); }

// ---------------- scratch ----------------
__device__ float g_pre_enc[BB*TSEQ*ATTD];
__device__ float g_e[BB*TSEQ];
__device__ float g_attc[BB*EPROJ];
__device__ float g_z0[BB*DUN], g_c0[BB*DUN], g_z1[BB*DUN], g_c1[BB*DUN];
__device__ float g_part[NSPLIT*BB*4096];
__device__ float g_zs[BB*LP1*DUN];
__device__ float g_logits[(size_t)NROWS*ODIMC];
__device__ float g_rownll[NROWS];
__device__ int   g_rowhit[NROWS];

__global__ void init_state(float* z0,float* c0,float* z1,float* c1){
    int i = blockIdx.x*blockDim.x + threadIdx.x;
    if (i < BB*DUN){ z0[i]=0.f; c0[i]=0.f; z1[i]=0.f; c1[i]=0.f; }
}

// ---------------- generic C[M,N] = act(A @ W^T + bias), 64x64 tiles ----------------
__global__ void sgemm_nt(const float* __restrict__ A, const float* __restrict__ W,
                         const float* __restrict__ bias, float* __restrict__ C,
                         int M, int N, int K, int act)
{
    __shared__ __align__(16) float As[16][68];
    __shared__ __align__(16) float Ws[16][68];
    int bm = blockIdx.x * 64, bn = blockIdx.y * 64;
    int tx = threadIdx.x & 15, ty = threadIdx.x >> 4;
    ull acc[4][2] = {{0ull,0ull},{0ull,0ull},{0ull,0ull},{0ull,0ull}};
    for (int k0 = 0; k0 < K; k0 += 16){
        #pragma unroll
        for (int j=0;j<4;j++){
            int i = threadIdx.x + j*256;
            int m = i >> 4, k = i & 15;
            int gm = bm + m;
            As[k][m] = (gm < M) ? A[(size_t)gm*K + k0 + k] : 0.f;
            int gn = bn + m;
            Ws[k][m] = (gn < N) ? W[(size_t)gn*K + k0 + k] : 0.f;
        }
        __syncthreads();
        #pragma unroll
        for (int k=0;k<16;k++){
            float4 a4 = *(const float4*)&As[k][ty*4];
            ulonglong2 w2 = *(const ulonglong2*)&Ws[k][tx*4];
            ull a;
            a = pack2(a4.x); fma2(acc[0][0],a,w2.x); fma2(acc[0][1],a,w2.y);
            a = pack2(a4.y); fma2(acc[1][0],a,w2.x); fma2(acc[1][1],a,w2.y);
            a = pack2(a4.z); fma2(acc[2][0],a,w2.x); fma2(acc[2][1],a,w2.y);
            a = pack2(a4.w); fma2(acc[3][0],a,w2.x); fma2(acc[3][1],a,w2.y);
        }
        __syncthreads();
    }
    #pragma unroll
    for (int i=0;i<4;i++){
        int m = bm + ty*4 + i;
        if (m >= M) continue;
        #pragma unroll
        for (int jp=0;jp<2;jp++){
            float2 v = unpack2(acc[i][jp]);
            int n = bn + tx*4 + jp*2;
            if (n < N){   float r = v.x + (bias?bias[n]:0.f);   if(act) r=tanhf(r); C[(size_t)m*N+n]   = r; }
            if (n+1 < N){ float r = v.y + (bias?bias[n+1]:0.f); if(act) r=tanhf(r); C[(size_t)m*N+n+1] = r; }
        }
    }
}

// ---------------- scores: e[b][t] = mask( 2 * pre_enc[b,t,:] . tanh(Wdec @ z0[b]) ) ----------------
// grid (32 b, 2 t-chunks), 256 threads
__global__ void scores_kernel(const float* __restrict__ pre_enc, const float* __restrict__ Wdec,
                              const float* __restrict__ z0, const int* __restrict__ hlens,
                              float* __restrict__ e_out)
{
    int b = blockIdx.x, tc = blockIdx.y;
    int tid = threadIdx.x, warp = tid >> 5, lane = tid & 31;
    __shared__ __align__(16) float z_s[DUN];
    __shared__ __align__(16) float dec_s[ATTD];
    int hlen = hlens[b];

    #pragma unroll
    for (int i=0;i<4;i++) z_s[tid + i*256] = z0[b*DUN + tid + i*256];
    __syncthreads();

    for (int a = warp; a < ATTD; a += 8){
        const float* wr = Wdec + (size_t)a*DUN;
        ull acc = 0ull;
        #pragma unroll
        for (int i=0;i<16;i++){
            int k = (lane<<1) + (i<<6);
            fma2(acc, *(const ull*)(wr + k), *(const ull*)(z_s + k));
        }
        float2 p = unpack2(acc);
        float v = p.x + p.y;
        #pragma unroll
        for (int o=16;o;o>>=1) v += __shfl_xor_sync(0xffffffffu, v, o);
        if (lane==0) dec_s[a] = tanhf(v);
    }
    __syncthreads();

    int t = tc*256 + tid;
    const float* pr = pre_enc + ((size_t)(b*TSEQ) + t)*ATTD;
    ull c0=0ull,c1=0ull,c2=0ull,c3=0ull;
    #pragma unroll
    for (int a=0; a<ATTD; a+=8){
        fma2(c0, *(const ull*)(pr+a),   *(const ull*)(dec_s+a));
        fma2(c1, *(const ull*)(pr+a+2), *(const ull*)(dec_s+a+2));
        fma2(c2, *(const ull*)(pr+a+4), *(const ull*)(dec_s+a+4));
        fma2(c3, *(const ull*)(pr+a+6), *(const ull*)(dec_s+a+6));
    }
    float2 p0 = unpack2(c0), p1 = unpack2(c1), p2 = unpack2(c2), p3 = unpack2(c3);
    float e = (p0.x+p0.y)+(p1.x+p1.y)+(p2.x+p2.y)+(p3.x+p3.y);
    e_out[b*TSEQ + t] = (t < hlen) ? 2.0f*e : -1e30f;
}

// ---------------- softmax + att_c: grid (32 b, 4 d-chunks of 128), 256 threads ----------------
__global__ void attc_kernel(const float* __restrict__ e_in, const float* __restrict__ hs,
                            float* __restrict__ attc)
{
    int b = blockIdx.x, dc = blockIdx.y;
    int tid = threadIdx.x, lane = tid & 31, warp = tid >> 5;
    __shared__ float w_s[TSEQ];
    __shared__ float red_s[10];
    __shared__ float part_s[256];

    float e0 = e_in[b*TSEQ + tid];
    float e1 = e_in[b*TSEQ + 256 + tid];
    float lm = fmaxf(e0, e1);
    #pragma unroll
    for (int o=16;o;o>>=1) lm = fmaxf(lm, __shfl_xor_sync(0xffffffffu, lm, o));
    if (lane==0) red_s[warp] = lm;
    __syncthreads();
    if (tid==0){ float mm=red_s[0]; for (int w=1;w<8;w++) mm=fmaxf(mm,red_s[w]); red_s[8]=mm; }
    __syncthreads();
    float m = red_s[8];
    float p0 = expf(e0 - m), p1 = expf(e1 - m);
    w_s[tid] = p0; w_s[tid+256] = p1;
    float ps = p0 + p1;
    #pragma unroll
    for (int o=16;o;o>>=1) ps += __shfl_xor_sync(0xffffffffu, ps, o);
    if (lane==0) red_s[warp] = ps;
    __syncthreads();
    if (tid==0){ float s=0.f; for (int w=0;w<8;w++) s+=red_s[w]; red_s[9]=1.0f/s; }
    __syncthreads();
    float inv = red_s[9];

    int di = tid & 127, s = tid >> 7;
    int d = dc*128 + di;
    const float* hb = hs + ((size_t)(b*TSEQ) + s*256)*EPROJ + d;
    const float* wp = w_s + s*256;
    float a0=0.f,a1=0.f,a2=0.f,a3=0.f;
    #pragma unroll 4
    for (int t=0; t<256; t+=4){
        a0 += wp[t]   * hb[(size_t)(t)*EPROJ];
        a1 += wp[t+1] * hb[(size_t)(t+1)*EPROJ];
        a2 += wp[t+2] * hb[(size_t)(t+2)*EPROJ];
        a3 += wp[t+3] * hb[(size_t)(t+3)*EPROJ];
    }
    part_s[tid] = (a0+a1)+(a2+a3);
    __syncthreads();
    if (s == 0) attc[b*EPROJ + d] = inv * (part_s[di] + part_s[128 + di]);
}

// ---------------- LSTM gates GEMM, 16-way k-split ----------------
// grid (32 n-tiles of 128, 16 splits), 256 threads. BM=32, BN=128.
// A (32 x KS) staged in smem; W double-buffered (register staging + smem transpose).
template<int LAYER>
__global__ void lstm_gates(const float* __restrict__ embed_w, const int* __restrict__ ys,
                           const float* __restrict__ attc, const float* __restrict__ z0,
                           const float* __restrict__ z1,
                           const float* __restrict__ Wih, const float* __restrict__ Whh,
                           float* __restrict__ part, int t)
{
    constexpr int KS  = (LAYER==0) ? 160 : 128;   // 2560/16 or 2048/16
    constexpr int NIT = KS / 16;
    __shared__ __align__(16) float A_s[KS][32];
    __shared__ __align__(16) float Ws[2][16][132];

    int tid = threadIdx.x;
    int bn = blockIdx.x * 128;
    int s  = blockIdx.y;
    int K0 = s * KS;

    // stage A (gather-concat) : A_s[k][m] = A(m, K0+k)
    for (int idx = tid; idx < KS*32; idx += 256){
        int k = idx >> 5, m = idx & 31;
        int kg = K0 + k;
        float v;
        if (LAYER==0){
            if (kg < DUN){ int tok = (t==0)?SOSEOS:ys[m*LLEN + (t-1)]; v = embed_w[(size_t)tok*DUN + kg]; }
            else if (kg < DUN+EPROJ) v = attc[m*EPROJ + (kg-DUN)];
            else v = z0[m*DUN + (kg-DUN-EPROJ)];
        } else {
            v = (kg < DUN) ? z0[m*DUN + kg] : z1[m*DUN + (kg-DUN)];
        }
        A_s[k][m] = v;
    }

    // W tile loader: tile it covers k = K0+it*16 .. +15, n = bn..bn+127
    int n0 = (tid >> 2);            // 0..63
    int c  = (tid & 3);             // float4 index along k
    float4 r0, r1;
    {
        int kg = K0 + 0*16 + c*4;
        int na = bn + n0, nb = bn + n0 + 64;
        if (LAYER==0){
            const float* pa = (kg < 1536) ? (Wih + (size_t)na*2560 + kg) : (Whh + (size_t)na*1024 + (kg-1536));
            const float* pb = (kg < 1536) ? (Wih + (size_t)nb*2560 + kg) : (Whh + (size_t)nb*1024 + (kg-1536));
            r0 = *(const float4*)pa; r1 = *(const float4*)pb;
        } else {
            const float* pa = (kg < 1024) ? (Wih + (size_t)na*1024 + kg) : (Whh + (size_t)na*1024 + (kg-1024));
            const float* pb = (kg < 1024) ? (Wih + (size_t)nb*1024 + kg) : (Whh + (size_t)nb*1024 + (kg-1024));
            r0 = *(const float4*)pa; r1 = *(const float4*)pb;
        }
    }
    // STS tile 0 (transposed: Ws[k][n])
    Ws[0][c*4+0][n0] = r0.x; Ws[0][c*4+1][n0] = r0.y; Ws[0][c*4+2][n0] = r0.z; Ws[0][c*4+3][n0] = r0.w;
    Ws[0][c*4+0][n0+64] = r1.x; Ws[0][c*4+1][n0+64] = r1.y; Ws[0][c*4+2][n0+64] = r1.z; Ws[0][c*4+3][n0+64] = r1.w;
    __syncthreads();

    int tx = tid & 31, ty = tid >> 5;   // n = tx*4.., m = ty*4..
    ull acc[4][2] = {{0ull,0ull},{0ull,0ull},{0ull,0ull},{0ull,0ull}};

    for (int it = 0; it < NIT; it++){
        if (it + 1 < NIT){
            int kg = K0 + (it+1)*16 + c*4;
            int na = bn + n0, nb = bn + n0 + 64;
            if (LAYER==0){
                const float* pa = (kg < 1536) ? (Wih + (size_t)na*2560 + kg) : (Whh + (size_t)na*1024 + (kg-1536));
                const float* pb = (kg < 1536) ? (Wih + (size_t)nb*2560 + kg) : (Whh + (size_t)nb*1024 + (kg-1536));
                r0 = *(const float4*)pa; r1 = *(const float4*)pb;
            } else {
                const float* pa = (kg < 1024) ? (Wih + (size_t)na*1024 + kg) : (Whh + (size_t)na*1024 + (kg-1024));
                const float* pb = (kg < 1024) ? (Wih + (size_t)nb*1024 + kg) : (Whh + (size_t)nb*1024 + (kg-1024));
                r0 = *(const float4*)pa; r1 = *(const float4*)pb;
            }
        }
        int cur = it & 1;
        #pragma unroll
        for (int k=0;k<16;k++){
            float4 a4 = *(const float4*)&A_s[it*16 + k][ty*4];
            ulonglong2 w2a = *(const ulonglong2*)&Ws[cur][k][tx*4];
            ull a;
            a = pack2(a4.x); fma2(acc[0][0],a,w2a.x); fma2(acc[0][1],a,w2a.y);
            a = pack2(a4.y); fma2(acc[1][0],a,w2a.x); fma2(acc[1][1],a,w2a.y);
            a = pack2(a4.z); fma2(acc[2][0],a,w2a.x); fma2(acc[2][1],a,w2a.y);
            a = pack2(a4.w); fma2(acc[3][0],a,w2a.x); fma2(acc[3][1],a,w2a.y);
        }
        __syncthreads();
        if (it + 1 < NIT){
            int nxt = 1 - cur;
            Ws[nxt][c*4+0][n0] = r0.x; Ws[nxt][c*4+1][n0] = r0.y; Ws[nxt][c*4+2][n0] = r0.z; Ws[nxt][c*4+3][n0] = r0.w;
            Ws[nxt][c*4+0][n0+64] = r1.x; Ws[nxt][c*4+1][n0+64] = r1.y; Ws[nxt][c*4+2][n0+64] = r1.z; Ws[nxt][c*4+3][n0+64] = r1.w;
            __syncthreads();
        }
    }

    float* dst = part + (size_t)s*BB*4096;
    #pragma unroll
    for (int i=0;i<4;i++){
        int m = ty*4 + i;
        #pragma unroll
        for (int jp=0;jp<2;jp++){
            float2 v = unpack2(acc[i][jp]);
            int n = bn + tx*4 + jp*2;
            dst[m*4096 + n]     = v.x;
            dst[m*4096 + n + 1] = v.y;
        }
    }
}

// ---------------- combine 16 k-splits + biases + LSTM cell ----------------
__global__ void lstm_cell(const float* __restrict__ part, const float* __restrict__ bih,
                          const float* __restrict__ bhh, float* __restrict__ z,
                          float* __restrict__ c, float* __restrict__ zs_out, int t)
{
    int idx = blockIdx.x*blockDim.x + threadIdx.x;
    if (idx >= BB*DUN) return;
    int b = idx >> 10, j = idx & 1023;
    float gi = bih[j]        + bhh[j];
    float gf = bih[1024 + j] + bhh[1024 + j];
    float gg = bih[2048 + j] + bhh[2048 + j];
    float go = bih[3072 + j] + bhh[3072 + j];
    #pragma unroll
    for (int s = 0; s < NSPLIT; s++){
        const float* p = part + ((size_t)(s*BB + b))*4096;
        gi += p[j]; gf += p[1024 + j]; gg += p[2048 + j]; go += p[3072 + j];
    }
    float cn = sigmoidf_(gf) * c[idx] + sigmoidf_(gi) * tanhf(gg);
    float zn = sigmoidf_(go) * tanhf(cn);
    c[idx] = cn; z[idx] = zn;
    if (zs_out) zs_out[((size_t)b*LP1 + t)*DUN + j] = zn;
}

// ---------------- per-row logsumexp / argmax / nll ----------------
__global__ void rowloss(const float* __restrict__ logits, const int* __restrict__ ys,
                        float* __restrict__ rownll, int* __restrict__ rowhit)
{
    int r = blockIdx.x, tid = threadIdx.x;
    const float* row = logits + (size_t)r*ODIMC;
    __shared__ float sv[256]; __shared__ int si[256]; __shared__ double sd[256];
    float vmax = -INFINITY; int vidx = ODIMC;
    for (int i=tid;i<ODIMC;i+=256){ float v=row[i]; if (v>vmax){ vmax=v; vidx=i; } }
    sv[tid]=vmax; si[tid]=vidx; __syncthreads();
    for (int s=128;s;s>>=1){
        if (tid<s){
            float v2=sv[tid+s]; int i2=si[tid+s];
            if (v2>sv[tid] || (v2==sv[tid] && i2<si[tid])){ sv[tid]=v2; si[tid]=i2; }
        }
        __syncthreads();
    }
    float m = sv[0]; int amax = si[0];
    double ps = 0.0;
    for (int i=tid;i<ODIMC;i+=256) ps += (double)expf(row[i]-m);
    sd[tid]=ps; __syncthreads();
    for (int s=128;s;s>>=1){ if (tid<s) sd[tid]+=sd[tid+s]; __syncthreads(); }
    if (tid==0){
        int b = r / LP1, l = r % LP1;
        int tgt = (l < LLEN) ? ys[b*LLEN + l] : SOSEOS;
        double lse = (double)m + log(sd[0]);
        rownll[r] = (float)(lse - (double)row[tgt]);
        rowhit[r] = (amax == tgt) ? 1 : 0;
    }
}

__global__ void finalize(const float* __restrict__ rownll, const int* __restrict__ rowhit,
                         float* __restrict__ out, int out_size)
{
    __shared__ double sd[256]; __shared__ int sh[256];
    int tid = threadIdx.x;
    double s = 0.0; int h = 0;
    for (int i=tid;i<NROWS;i+=256){ s += (double)rownll[i]; h += rowhit[i]; }
    sd[tid]=s; sh[tid]=h; __syncthreads();
    for (int st=128;st;st>>=1){ if (tid<st){ sd[tid]+=sd[tid+st]; sh[tid]+=sh[tid+st]; } __syncthreads(); }
    if (tid==0){
        double loss = sd[0]/(double)NROWS * (double)LLEN;
        double acc  = (double)sh[0]/(double)NROWS;
        double ppl  = exp(loss/(double)BB);
        if (out_size>0) out[0]=(float)loss;
        if (out_size>1) out[1]=(float)acc;
        if (out_size>2) out[2]=(float)ppl;
    }
    for (int i=3+tid;i<out_size;i+=256) out[i]=0.f;
}

// ---------------- launcher ----------------
static void* symaddr(const void* sym){ void* p=nullptr; cudaGetSymbolAddress(&p, sym); return p; }

extern "C" void kernel_launch(void* const* d_in, const int* in_sizes, int n_in,
                              void* d_out, int out_size)
{
    const float* hs    = (const float*)d_in[0];
    const int*   hlens = (const int*)  d_in[1];
    const int*   ys    = (const int*)  d_in[2];
    const float* embed = (const float*)d_in[3];
    const float* Wenc  = (const float*)d_in[4];
    const float* benc  = (const float*)d_in[5];
    const float* Wdec  = (const float*)d_in[6];
    const float* Wih0  = (const float*)d_in[7];
    const float* Whh0  = (const float*)d_in[8];
    const float* bih0  = (const float*)d_in[9];
    const float* bhh0  = (const float*)d_in[10];
    const float* Wih1  = (const float*)d_in[11];
    const float* Whh1  = (const float*)d_in[12];
    const float* bih1  = (const float*)d_in[13];
    const float* bhh1  = (const float*)d_in[14];
    const float* Wout  = (const float*)d_in[15];
    const float* bout  = (const float*)d_in[16];
    float* out = (float*)d_out;

    float* pre_enc = (float*)symaddr(g_pre_enc);
    float* e_buf   = (float*)symaddr(g_e);
    float* attc    = (float*)symaddr(g_attc);
    float* z0      = (float*)symaddr(g_z0);
    float* c0      = (float*)symaddr(g_c0);
    float* z1      = (float*)symaddr(g_z1);
    float* c1      = (float*)symaddr(g_c1);
    float* part    = (float*)symaddr(g_part);
    float* zs      = (float*)symaddr(g_zs);
    float* logits  = (float*)symaddr(g_logits);
    float* rownll  = (float*)symaddr(g_rownll);
    int*   rowhit  = (int*)  symaddr(g_rowhit);

    init_state<<<128,256>>>(z0,c0,z1,c1);

    // pre_enc = tanh(hs @ Wenc^T + benc):  [16384,320]
    sgemm_nt<<<dim3(256,5),256>>>(hs, Wenc, benc, pre_enc, BB*TSEQ, ATTD, EPROJ, 1);

    for (int t=0; t<LP1; t++){
        scores_kernel<<<dim3(BB,2),256>>>(pre_enc, Wdec, z0, hlens, e_buf);
        attc_kernel<<<dim3(BB,4),256>>>(e_buf, hs, attc);
        lstm_gates<0><<<dim3(32,NSPLIT),256>>>(embed, ys, attc, z0, z1, Wih0, Whh0, part, t);
        lstm_cell<<<128,256>>>(part, bih0, bhh0, z0, c0, (float*)nullptr, t);
        lstm_gates<1><<<dim3(32,NSPLIT),256>>>(embed, ys, attc, z0, z1, Wih1, Whh1, part, t);
        lstm_cell<<<128,256>>>(part, bih1, bhh1, z1, c1, zs, t);
    }

    // logits = zs @ Wout^T + bout : [4128, 10000]
    sgemm_nt<<<dim3((NROWS+63)/64,(ODIMC+63)/64),256>>>(zs, Wout, bout, logits, NROWS, ODIMC, DUN, 0);

    rowloss<<<NROWS,256>>>(logits, ys, rownll, rowhit);
    finalize<<<1,256>>>(rownll, rowhit, out, out_size);
}

// round 4
// speedup vs baseline: 3.8564x; 1.1142x over previous
#include <cuda_runtime.h>
#include <cuda_bf16.h>
#include <math.h>

#define BB      32
#define TSEQ    512
#define EPROJ   512
#define DUN     1024
#define ODIMC   10000
#define ATTD    320
#define LLEN    128
#define LP1     129
#define SOSEOS  9999
#define NROWS   (BB*LP1)   // 4128
#define NS      8          // k-splits for gates
#define KS0     320        // 2560/8
#define KS1     256        // 2048/8
#define ASTR    328        // A_s row stride (bf16 elems): 328/2=164, 164%32=4 -> conflict-free

typedef unsigned long long ull;
typedef unsigned int u32;

__device__ __forceinline__ ull pack2(float x){ ull r; asm("mov.b64 %0, {%1, %1};":"=l"(r):"f"(x)); return r; }
__device__ __forceinline__ void fma2(ull &a, ull x, ull y){ asm("fma.rn.f32x2 %0, %1, %2, %3;":"=l"(a):"l"(x),"l"(y),"l"(a)); }
__device__ __forceinline__ float2 unpack2(ull v){ float2 f; asm("mov.b64 {%0, %1}, %2;":"=f"(f.x),"=f"(f.y):"l"(v)); return f; }
__device__ __forceinline__ float sigmoidf_(float x){ return 1.0f/(1.0f+expf(-x)); }
__device__ __forceinline__ void mma_bf16(float* d, const u32* a, const u32* b){
    asm volatile("mma.sync.aligned.m16n8k16.row.col.f32.bf16.bf16.f32 "
        "{%0,%1,%2,%3},{%4,%5,%6,%7},{%8,%9},{%0,%1,%2,%3};"
        :"+f"(d[0]),"+f"(d[1]),"+f"(d[2]),"+f"(d[3])
        :"r"(a[0]),"r"(a[1]),"r"(a[2]),"r"(a[3]),"r"(b[0]),"r"(b[1]));
}

// ---------------- scratch ----------------
__device__ float g_pre_enc[BB*TSEQ*ATTD];
__device__ float g_e[BB*TSEQ];
__device__ float g_attc[BB*EPROJ];
__device__ float g_z0[BB*DUN], g_c0[BB*DUN], g_z1[BB*DUN], g_c1[BB*DUN];
__device__ float g_part[2*NS*BB*4096];
__device__ __nv_bfloat16 g_zsb[NROWS*DUN];
__device__ __nv_bfloat16 g_W0[4096*2560];
__device__ __nv_bfloat16 g_W1[4096*2048];
__device__ __nv_bfloat16 g_Wo[(size_t)ODIMC*DUN];
__device__ float g_logits[(size_t)NROWS*ODIMC];
__device__ float g_rownll[NROWS];
__device__ int   g_rowhit[NROWS];

__global__ void init_state(float* z0,float* c0,float* z1,float* c1){
    int i = blockIdx.x*blockDim.x + threadIdx.x;
    if (i < BB*DUN){ z0[i]=0.f; c0[i]=0.f; z1[i]=0.f; c1[i]=0.f; }
}

// ---------------- fp32 -> bf16 concat conversion (rows of a then b per output row) ----------------
__global__ void convcat(const float* __restrict__ a, const float* __restrict__ b,
                        __nv_bfloat16* __restrict__ dst, int N, int K1, int K2)
{
    int K = K1 + K2;
    size_t total = (size_t)N*K;
    for (size_t i = (size_t)blockIdx.x*blockDim.x + threadIdx.x; i < total;
         i += (size_t)gridDim.x*blockDim.x){
        size_t n = i / K; int k = (int)(i - n*K);
        float v = (k < K1) ? a[n*(size_t)K1 + k] : b[n*(size_t)K2 + (k - K1)];
        dst[i] = __float2bfloat16(v);
    }
}

// ---------------- fp32 GEMM for pre_enc: C = tanh(A @ W^T + bias), 64x64 tiles ----------------
__global__ void sgemm_nt(const float* __restrict__ A, const float* __restrict__ W,
                         const float* __restrict__ bias, float* __restrict__ C,
                         int M, int N, int K, int act)
{
    __shared__ __align__(16) float As[16][68];
    __shared__ __align__(16) float Ws[16][68];
    int bm = blockIdx.x * 64, bn = blockIdx.y * 64;
    int tx = threadIdx.x & 15, ty = threadIdx.x >> 4;
    ull acc[4][2] = {{0ull,0ull},{0ull,0ull},{0ull,0ull},{0ull,0ull}};
    for (int k0 = 0; k0 < K; k0 += 16){
        #pragma unroll
        for (int j=0;j<4;j++){
            int i = threadIdx.x + j*256;
            int m = i >> 4, k = i & 15;
            int gm = bm + m;
            As[k][m] = (gm < M) ? A[(size_t)gm*K + k0 + k] : 0.f;
            int gn = bn + m;
            Ws[k][m] = (gn < N) ? W[(size_t)gn*K + k0 + k] : 0.f;
        }
        __syncthreads();
        #pragma unroll
        for (int k=0;k<16;k++){
            float4 a4 = *(const float4*)&As[k][ty*4];
            ulonglong2 w2 = *(const ulonglong2*)&Ws[k][tx*4];
            ull a;
            a = pack2(a4.x); fma2(acc[0][0],a,w2.x); fma2(acc[0][1],a,w2.y);
            a = pack2(a4.y); fma2(acc[1][0],a,w2.x); fma2(acc[1][1],a,w2.y);
            a = pack2(a4.z); fma2(acc[2][0],a,w2.x); fma2(acc[2][1],a,w2.y);
            a = pack2(a4.w); fma2(acc[3][0],a,w2.x); fma2(acc[3][1],a,w2.y);
        }
        __syncthreads();
    }
    #pragma unroll
    for (int i=0;i<4;i++){
        int m = bm + ty*4 + i;
        if (m >= M) continue;
        #pragma unroll
        for (int jp=0;jp<2;jp++){
            float2 v = unpack2(acc[i][jp]);
            int n = bn + tx*4 + jp*2;
            if (n < N){   float r = v.x + (bias?bias[n]:0.f);   if(act) r=tanhf(r); C[(size_t)m*N+n]   = r; }
            if (n+1 < N){ float r = v.y + (bias?bias[n+1]:0.f); if(act) r=tanhf(r); C[(size_t)m*N+n+1] = r; }
        }
    }
}

// ---------------- scores: e[b][t] = mask( 2 * pre_enc[b,t,:] . tanh(Wdec @ z0[b]) ) ----------------
__global__ void scores_kernel(const float* __restrict__ pre_enc, const float* __restrict__ Wdec,
                              const float* __restrict__ z0, const int* __restrict__ hlens,
                              float* __restrict__ e_out)
{
    int b = blockIdx.x, tc = blockIdx.y;
    int tid = threadIdx.x, warp = tid >> 5, lane = tid & 31;
    __shared__ __align__(16) float z_s[DUN];
    __shared__ __align__(16) float dec_s[ATTD];
    int hlen = hlens[b];

    #pragma unroll
    for (int i=0;i<4;i++) z_s[tid + i*256] = z0[b*DUN + tid + i*256];
    __syncthreads();

    for (int a = warp; a < ATTD; a += 8){
        const float* wr = Wdec + (size_t)a*DUN;
        ull acc = 0ull;
        #pragma unroll
        for (int i=0;i<16;i++){
            int k = (lane<<1) + (i<<6);
            fma2(acc, *(const ull*)(wr + k), *(const ull*)(z_s + k));
        }
        float2 p = unpack2(acc);
        float v = p.x + p.y;
        #pragma unroll
        for (int o=16;o;o>>=1) v += __shfl_xor_sync(0xffffffffu, v, o);
        if (lane==0) dec_s[a] = tanhf(v);
    }
    __syncthreads();

    int t = tc*256 + tid;
    const float* pr = pre_enc + ((size_t)(b*TSEQ) + t)*ATTD;
    ull c0=0ull,c1=0ull,c2=0ull,c3=0ull;
    #pragma unroll
    for (int a=0; a<ATTD; a+=8){
        fma2(c0, *(const ull*)(pr+a),   *(const ull*)(dec_s+a));
        fma2(c1, *(const ull*)(pr+a+2), *(const ull*)(dec_s+a+2));
        fma2(c2, *(const ull*)(pr+a+4), *(const ull*)(dec_s+a+4));
        fma2(c3, *(const ull*)(pr+a+6), *(const ull*)(dec_s+a+6));
    }
    float2 p0 = unpack2(c0), p1 = unpack2(c1), p2 = unpack2(c2), p3 = unpack2(c3);
    float e = (p0.x+p0.y)+(p1.x+p1.y)+(p2.x+p2.y)+(p3.x+p3.y);
    e_out[b*TSEQ + t] = (t < hlen) ? 2.0f*e : -1e30f;
}

// ---------------- softmax + att_c: grid (32 b, 8 d-chunks of 64), 256 threads ----------------
__global__ void attc_kernel(const float* __restrict__ e_in, const float* __restrict__ hs,
                            const int* __restrict__ hlens, float* __restrict__ attc)
{
    int b = blockIdx.x, dc = blockIdx.y;
    int tid = threadIdx.x, lane = tid & 31, warp = tid >> 5;
    __shared__ float w_s[TSEQ];
    __shared__ float red_s[10];
    __shared__ float part_s[256];

    float e0 = e_in[b*TSEQ + tid];
    float e1 = e_in[b*TSEQ + 256 + tid];
    float lm = fmaxf(e0, e1);
    #pragma unroll
    for (int o=16;o;o>>=1) lm = fmaxf(lm, __shfl_xor_sync(0xffffffffu, lm, o));
    if (lane==0) red_s[warp] = lm;
    __syncthreads();
    if (tid==0){ float mm=red_s[0]; for (int w=1;w<8;w++) mm=fmaxf(mm,red_s[w]); red_s[8]=mm; }
    __syncthreads();
    float m = red_s[8];
    float p0 = expf(e0 - m), p1 = expf(e1 - m);
    w_s[tid] = p0; w_s[tid+256] = p1;
    float ps = p0 + p1;
    #pragma unroll
    for (int o=16;o;o>>=1) ps += __shfl_xor_sync(0xffffffffu, ps, o);
    if (lane==0) red_s[warp] = ps;
    __syncthreads();
    if (tid==0){ float s=0.f; for (int w=0;w<8;w++) s+=red_s[w]; red_s[9]=1.0f/s; }
    __syncthreads();
    float inv = red_s[9];

    int hlen = hlens[b];
    int di = tid & 63, s = tid >> 6;
    int d = dc*64 + di;
    const float* hb = hs + ((size_t)(b*TSEQ) + s*128)*EPROJ + d;
    const float* wp = w_s + s*128;
    int tmax = hlen - s*128; if (tmax > 128) tmax = 128; if (tmax < 0) tmax = 0;
    float a0=0.f, a1=0.f;
    int t = 0;
    for (; t+1 < tmax; t+=2){
        a0 += wp[t]   * hb[(size_t)t*EPROJ];
        a1 += wp[t+1] * hb[(size_t)(t+1)*EPROJ];
    }
    if (t < tmax) a0 += wp[t]*hb[(size_t)t*EPROJ];
    part_s[tid] = a0 + a1;
    __syncthreads();
    if (s == 0)
        attc[b*EPROJ + d] = inv * (part_s[di] + part_s[64+di] + part_s[128+di] + part_s[192+di]);
}

// ---------------- bf16 MMA gates: both layers in one launch (layer0@t, layer1@t-1) ----------------
// grid (32 n-tiles of 128, NS splits, 2 layers), 256 threads.
__global__ void gates_mma(const float* __restrict__ embed, const int* __restrict__ ys,
                          const float* __restrict__ attcv, const float* __restrict__ z0,
                          const float* __restrict__ z1,
                          const __nv_bfloat16* __restrict__ W0cat,
                          const __nv_bfloat16* __restrict__ W1cat,
                          float* __restrict__ part, int t)
{
    int layer = blockIdx.z;
    if (layer==0 && t>=LP1) return;
    if (layer==1 && t==0)  return;
    const int KS = layer ? KS1 : KS0;
    const int K  = layer ? 2048 : 2560;
    const __nv_bfloat16* W = layer ? W1cat : W0cat;

    __shared__ __align__(16) __nv_bfloat16 A_s[32][ASTR];
    int tid = threadIdx.x;
    int bn = blockIdx.x * 128;
    int s  = blockIdx.y;
    int K0 = s * KS;

    // gather-concat A slice [32][KS] -> bf16 smem
    for (int idx = tid; idx < 32*KS; idx += 256){
        int mm = idx / KS, k = idx - mm*KS;
        int kg = K0 + k;
        float v;
        if (layer==0){
            if (kg < 1024){ int tok = (t==0)?SOSEOS:ys[mm*LLEN + (t-1)]; v = embed[(size_t)tok*DUN + kg]; }
            else if (kg < 1536) v = attcv[mm*EPROJ + (kg-1024)];
            else                v = z0[mm*DUN + (kg-1536)];
        } else {
            v = (kg < 1024) ? z0[mm*DUN + kg] : z1[mm*DUN + (kg-1024)];
        }
        A_s[mm][k] = __float2bfloat16(v);
    }
    __syncthreads();

    int w = tid >> 5, l = tid & 31, gid = l >> 2, tg = l & 3;
    float acc[2][2][4];
    #pragma unroll
    for (int i=0;i<2;i++)
        #pragma unroll
        for (int j=0;j<2;j++)
            #pragma unroll
            for (int q=0;q<4;q++) acc[i][j][q] = 0.f;

    for (int kk = 0; kk < KS; kk += 16){
        u32 a[2][4], bf[2][2];
        #pragma unroll
        for (int mt=0; mt<2; mt++){
            int r0 = mt*16 + gid;
            a[mt][0] = *(const u32*)&A_s[r0  ][kk + 2*tg];
            a[mt][1] = *(const u32*)&A_s[r0+8][kk + 2*tg];
            a[mt][2] = *(const u32*)&A_s[r0  ][kk + 2*tg + 8];
            a[mt][3] = *(const u32*)&A_s[r0+8][kk + 2*tg + 8];
        }
        int kg = K0 + kk + 2*tg;
        #pragma unroll
        for (int nt=0; nt<2; nt++){
            const __nv_bfloat16* wp = W + (size_t)(bn + w*16 + nt*8 + gid)*K + kg;
            bf[nt][0] = *(const u32*)wp;
            bf[nt][1] = *(const u32*)(wp + 8);
        }
        #pragma unroll
        for (int mt=0; mt<2; mt++)
            #pragma unroll
            for (int nt=0; nt<2; nt++)
                mma_bf16(acc[mt][nt], a[mt], bf[nt]);
    }

    float* dst = part + ((size_t)(layer*NS + s))*32*4096;
    #pragma unroll
    for (int mt=0; mt<2; mt++){
        #pragma unroll
        for (int nt=0; nt<2; nt++){
            int row = mt*16 + gid;
            int col = bn + w*16 + nt*8 + 2*tg;
            float2 v0 = make_float2(acc[mt][nt][0], acc[mt][nt][1]);
            float2 v1 = make_float2(acc[mt][nt][2], acc[mt][nt][3]);
            *(float2*)&dst[(size_t)row*4096 + col]     = v0;
            *(float2*)&dst[(size_t)(row+8)*4096 + col] = v1;
        }
    }
}

// ---------------- combine splits + biases + LSTM cell, both layers ----------------
__global__ void cell2(const float* __restrict__ part,
                      const float* __restrict__ bih0, const float* __restrict__ bhh0,
                      const float* __restrict__ bih1, const float* __restrict__ bhh1,
                      float* __restrict__ z0, float* __restrict__ c0,
                      float* __restrict__ z1, float* __restrict__ c1,
                      __nv_bfloat16* __restrict__ zsb, int t)
{
    int layer = blockIdx.y;
    if (layer==0 && t>=LP1) return;
    if (layer==1 && t==0)  return;
    int idx = blockIdx.x*256 + threadIdx.x;   // 0..32767
    int b = idx >> 10, j = idx & 1023;
    const float* bih = layer ? bih1 : bih0;
    const float* bhh = layer ? bhh1 : bhh0;
    float gi = bih[j]        + bhh[j];
    float gf = bih[1024 + j] + bhh[1024 + j];
    float gg = bih[2048 + j] + bhh[2048 + j];
    float go = bih[3072 + j] + bhh[3072 + j];
    const float* pb = part + (size_t)layer*NS*32*4096 + (size_t)b*4096 + j;
    #pragma unroll
    for (int s=0; s<NS; s++){
        const float* p = pb + (size_t)s*32*4096;
        gi += p[0]; gf += p[1024]; gg += p[2048]; go += p[3072];
    }
    float* z = layer ? z1 : z0;
    float* c = layer ? c1 : c0;
    float cn = sigmoidf_(gf) * c[idx] + sigmoidf_(gi) * tanhf(gg);
    float zn = sigmoidf_(go) * tanhf(cn);
    c[idx] = cn; z[idx] = zn;
    if (layer == 1) zsb[((size_t)b*LP1 + (t-1))*DUN + j] = __float2bfloat16(zn);
}

// ---------------- bf16 MMA logits: C[4128,10000] = zsb @ Wo^T + bout ----------------
// grid (ceil(M/128)=33, ceil(N/128)=79), 256 threads, warp tile 32m x 64n, no smem.
__global__ void logits_mma(const __nv_bfloat16* __restrict__ A, const __nv_bfloat16* __restrict__ Wo,
                           const float* __restrict__ bias, float* __restrict__ Cout)
{
    int bm = blockIdx.x*128, bn = blockIdx.y*128;
    int tid = threadIdx.x, w = tid >> 5, l = tid & 31, gid = l >> 2, tg = l & 3;
    int moff = (w & 3) * 32, noff = (w >> 2) * 64;

    float acc[2][8][4];
    #pragma unroll
    for (int i=0;i<2;i++)
        #pragma unroll
        for (int j=0;j<8;j++)
            #pragma unroll
            for (int q=0;q<4;q++) acc[i][j][q]=0.f;

    int mr[2][2];
    #pragma unroll
    for (int mt=0; mt<2; mt++){
        int r0 = bm + moff + mt*16 + gid, r1 = r0 + 8;
        mr[mt][0] = (r0 < NROWS) ? r0 : (NROWS-1);
        mr[mt][1] = (r1 < NROWS) ? r1 : (NROWS-1);
    }
    int nr[8];
    #pragma unroll
    for (int nt=0; nt<8; nt++){
        int n = bn + noff + nt*8 + gid;
        nr[nt] = (n < ODIMC) ? n : (ODIMC-1);
    }

    for (int kk = 0; kk < DUN; kk += 16){
        u32 a[2][4];
        #pragma unroll
        for (int mt=0; mt<2; mt++){
            const __nv_bfloat16* p0 = A + (size_t)mr[mt][0]*DUN + kk + 2*tg;
            const __nv_bfloat16* p1 = A + (size_t)mr[mt][1]*DUN + kk + 2*tg;
            a[mt][0] = *(const u32*)p0;
            a[mt][1] = *(const u32*)p1;
            a[mt][2] = *(const u32*)(p0 + 8);
            a[mt][3] = *(const u32*)(p1 + 8);
        }
        #pragma unroll
        for (int nt=0; nt<8; nt++){
            const __nv_bfloat16* wp = Wo + (size_t)nr[nt]*DUN + kk + 2*tg;
            u32 bf[2];
            bf[0] = *(const u32*)wp;
            bf[1] = *(const u32*)(wp + 8);
            mma_bf16(acc[0][nt], a[0], bf);
            mma_bf16(acc[1][nt], a[1], bf);
        }
    }

    #pragma unroll
    for (int mt=0; mt<2; mt++){
        #pragma unroll
        for (int nt=0; nt<8; nt++){
            int row0 = bm + moff + mt*16 + gid;
            int col  = bn + noff + nt*8 + 2*tg;
            if (col < ODIMC){
                float b0 = bias[col], b1 = bias[col+1];
                if (row0 < NROWS){
                    float2 v = make_float2(acc[mt][nt][0] + b0, acc[mt][nt][1] + b1);
                    *(float2*)&Cout[(size_t)row0*ODIMC + col] = v;
                }
                if (row0 + 8 < NROWS){
                    float2 v = make_float2(acc[mt][nt][2] + b0, acc[mt][nt][3] + b1);
                    *(float2*)&Cout[(size_t)(row0+8)*ODIMC + col] = v;
                }
            }
        }
    }
}

// ---------------- per-row logsumexp / argmax / nll ----------------
__global__ void rowloss(const float* __restrict__ logits, const int* __restrict__ ys,
                        float* __restrict__ rownll, int* __restrict__ rowhit)
{
    int r = blockIdx.x, tid = threadIdx.x;
    const float* row = logits + (size_t)r*ODIMC;
    __shared__ float sv[256]; __shared__ int si[256]; __shared__ double sd[256];
    float vmax = -INFINITY; int vidx = ODIMC;
    for (int i=tid;i<ODIMC;i+=256){ float v=row[i]; if (v>vmax){ vmax=v; vidx=i; } }
    sv[tid]=vmax; si[tid]=vidx; __syncthreads();
    for (int s=128;s;s>>=1){
        if (tid<s){
            float v2=sv[tid+s]; int i2=si[tid+s];
            if (v2>sv[tid] || (v2==sv[tid] && i2<si[tid])){ sv[tid]=v2; si[tid]=i2; }
        }
        __syncthreads();
    }
    float m = sv[0]; int amax = si[0];
    double ps = 0.0;
    for (int i=tid;i<ODIMC;i+=256) ps += (double)expf(row[i]-m);
    sd[tid]=ps; __syncthreads();
    for (int s=128;s;s>>=1){ if (tid<s) sd[tid]+=sd[tid+s]; __syncthreads(); }
    if (tid==0){
        int b = r / LP1, ll = r % LP1;
        int tgt = (ll < LLEN) ? ys[b*LLEN + ll] : SOSEOS;
        double lse = (double)m + log(sd[0]);
        rownll[r] = (float)(lse - (double)row[tgt]);
        rowhit[r] = (amax == tgt) ? 1 : 0;
    }
}

__global__ void finalize(const float* __restrict__ rownll, const int* __restrict__ rowhit,
                         float* __restrict__ out, int out_size)
{
    __shared__ double sd[256]; __shared__ int sh[256];
    int tid = threadIdx.x;
    double s = 0.0; int h = 0;
    for (int i=tid;i<NROWS;i+=256){ s += (double)rownll[i]; h += rowhit[i]; }
    sd[tid]=s; sh[tid]=h; __syncthreads();
    for (int st=128;st;st>>=1){ if (tid<st){ sd[tid]+=sd[tid+st]; sh[tid]+=sh[tid+st]; } __syncthreads(); }
    if (tid==0){
        double loss = sd[0]/(double)NROWS * (double)LLEN;
        double acc  = (double)sh[0]/(double)NROWS;
        double ppl  = exp(loss/(double)BB);
        if (out_size>0) out[0]=(float)loss;
        if (out_size>1) out[1]=(float)acc;
        if (out_size>2) out[2]=(float)ppl;
    }
    for (int i=3+tid;i<out_size;i+=256) out[i]=0.f;
}

// ---------------- launcher ----------------
static void* symaddr(const void* sym){ void* p=nullptr; cudaGetSymbolAddress(&p, sym); return p; }

extern "C" void kernel_launch(void* const* d_in, const int* in_sizes, int n_in,
                              void* d_out, int out_size)
{
    const float* hs    = (const float*)d_in[0];
    const int*   hlens = (const int*)  d_in[1];
    const int*   ys    = (const int*)  d_in[2];
    const float* embed = (const float*)d_in[3];
    const float* Wenc  = (const float*)d_in[4];
    const float* benc  = (const float*)d_in[5];
    const float* Wdec  = (const float*)d_in[6];
    const float* Wih0  = (const float*)d_in[7];
    const float* Whh0  = (const float*)d_in[8];
    const float* bih0  = (const float*)d_in[9];
    const float* bhh0  = (const float*)d_in[10];
    const float* Wih1  = (const float*)d_in[11];
    const float* Whh1  = (const float*)d_in[12];
    const float* bih1  = (const float*)d_in[13];
    const float* bhh1  = (const float*)d_in[14];
    const float* Wout  = (const float*)d_in[15];
    const float* bout  = (const float*)d_in[16];
    float* out = (float*)d_out;

    float* pre_enc = (float*)symaddr(g_pre_enc);
    float* e_buf   = (float*)symaddr(g_e);
    float* attc    = (float*)symaddr(g_attc);
    float* z0      = (float*)symaddr(g_z0);
    float* c0      = (float*)symaddr(g_c0);
    float* z1      = (float*)symaddr(g_z1);
    float* c1      = (float*)symaddr(g_c1);
    float* part    = (float*)symaddr(g_part);
    __nv_bfloat16* zsb = (__nv_bfloat16*)symaddr(g_zsb);
    __nv_bfloat16* W0b = (__nv_bfloat16*)symaddr(g_W0);
    __nv_bfloat16* W1b = (__nv_bfloat16*)symaddr(g_W1);
    __nv_bfloat16* Wob = (__nv_bfloat16*)symaddr(g_Wo);
    float* logits  = (float*)symaddr(g_logits);
    float* rownll  = (float*)symaddr(g_rownll);
    int*   rowhit  = (int*)  symaddr(g_rowhit);

    init_state<<<128,256>>>(z0,c0,z1,c1);

    // one-time (per replay) weight conversions: Wcat = [Wih | Whh] in bf16
    convcat<<<2048,256>>>(Wih0, Whh0, W0b, 4096, 1536, 1024);
    convcat<<<2048,256>>>(Wih1, Whh1, W1b, 4096, 1024, 1024);
    convcat<<<2048,256>>>(Wout, Wout, Wob, ODIMC, 1024, 0);

    // pre_enc = tanh(hs @ Wenc^T + benc):  [16384,320]
    sgemm_nt<<<dim3(256,5),256>>>(hs, Wenc, benc, pre_enc, BB*TSEQ, ATTD, EPROJ, 1);

    // software-pipelined recurrence: iteration t runs layer0@t and layer1@(t-1)
    for (int t = 0; t <= LP1; t++){
        if (t < LP1){
            scores_kernel<<<dim3(BB,2),256>>>(pre_enc, Wdec, z0, hlens, e_buf);
            attc_kernel<<<dim3(BB,8),256>>>(e_buf, hs, hlens, attc);
        }
        gates_mma<<<dim3(32,NS,2),256>>>(embed, ys, attc, z0, z1, W0b, W1b, part, t);
        cell2<<<dim3(128,2),256>>>(part, bih0,bhh0, bih1,bhh1, z0,c0,z1,c1, zsb, t);
    }

    // logits = zsb @ Wo^T + bout
    logits_mma<<<dim3(33,79),256>>>(zsb, Wob, bout, logits);

    rowloss<<<NROWS,256>>>(logits, ys, rownll, rowhit);
    finalize<<<1,256>>>(rownll, rowhit, out, out_size);
}

// round 6
// speedup vs baseline: 5.3677x; 1.3919x over previous
#include <cuda_runtime.h>
#include <cuda_bf16.h>
#include <math.h>

#define BB      32
#define TSEQ    512
#define EPROJ   512
#define DUN     1024
#define ODIMC   10000
#define ATTD    320
#define LLEN    128
#define LP1     129
#define SOSEOS  9999
#define NROWS   (BB*LP1)   // 4128
#define GRID    148
#define NSP0    5          // k-splits layer0 (2560 = 5*512)
#define NSP1    4          // k-splits layer1 (2048 = 4*512)

typedef unsigned long long ull;
typedef unsigned int u32;

__device__ __forceinline__ ull pack2(float x){ ull r; asm("mov.b64 %0, {%1, %1};":"=l"(r):"f"(x)); return r; }
__device__ __forceinline__ void fma2(ull &a, ull x, ull y){ asm("fma.rn.f32x2 %0, %1, %2, %3;":"=l"(a):"l"(x),"l"(y),"l"(a)); }
__device__ __forceinline__ float2 unpack2(ull v){ float2 f; asm("mov.b64 {%0, %1}, %2;":"=f"(f.x),"=f"(f.y):"l"(v)); return f; }
__device__ __forceinline__ float sigmoidf_(float x){ return 1.0f/(1.0f+expf(-x)); }
__device__ __forceinline__ void mma_bf16(float* d, const u32* a, const u32* b){
    asm volatile("mma.sync.aligned.m16n8k16.row.col.f32.bf16.bf16.f32 "
        "{%0,%1,%2,%3},{%4,%5,%6,%7},{%8,%9},{%0,%1,%2,%3};"
        :"+f"(d[0]),"+f"(d[1]),"+f"(d[2]),"+f"(d[3])
        :"r"(a[0]),"r"(a[1]),"r"(a[2]),"r"(a[3]),"r"(b[0]),"r"(b[1]));
}

// ---------------- scratch ----------------
__device__ float g_pre_enc[BB*TSEQ*ATTD];
__device__ float g_e[BB*TSEQ];
__device__ float g_attc[BB*EPROJ];
__device__ float g_z0[BB*DUN], g_c0[BB*DUN], g_z1[BB*DUN], g_c1[BB*DUN];
__device__ float g_part0[NSP0*BB*4096];
__device__ float g_part1[NSP1*BB*4096];
__device__ __nv_bfloat16 g_zsb[NROWS*DUN];
__device__ __nv_bfloat16 g_W0[4096*2560];
__device__ __nv_bfloat16 g_W1[4096*2048];
__device__ __nv_bfloat16 g_Wo[(size_t)ODIMC*DUN];
__device__ float g_logits[(size_t)NROWS*ODIMC];
__device__ float g_rownll[NROWS];
__device__ int   g_rowhit[NROWS];
__device__ unsigned g_cnt, g_gen;

__global__ void init_all(){
    int i = blockIdx.x*blockDim.x + threadIdx.x;
    if (i < BB*DUN){ g_z0[i]=0.f; g_c0[i]=0.f; g_z1[i]=0.f; g_c1[i]=0.f; }
    if (i == 0){ g_cnt = 0u; g_gen = 0u; }
}

// ---------------- fp32 -> bf16 concat conversion ----------------
__global__ void convcat(const float* __restrict__ a, const float* __restrict__ b,
                        __nv_bfloat16* __restrict__ dst, int N, int K1, int K2)
{
    int K = K1 + K2;
    size_t total = (size_t)N*K;
    for (size_t i = (size_t)blockIdx.x*blockDim.x + threadIdx.x; i < total;
         i += (size_t)gridDim.x*blockDim.x){
        size_t n = i / K; int k = (int)(i - n*K);
        float v = (k < K1) ? a[n*(size_t)K1 + k] : b[n*(size_t)K2 + (k - K1)];
        dst[i] = __float2bfloat16(v);
    }
}

// ---------------- fp32 GEMM for pre_enc: C = tanh(A @ W^T + bias) ----------------
__global__ void sgemm_nt(const float* __restrict__ A, const float* __restrict__ W,
                         const float* __restrict__ bias, float* __restrict__ C,
                         int M, int N, int K, int act)
{
    __shared__ __align__(16) float As[16][68];
    __shared__ __align__(16) float Ws[16][68];
    int bm = blockIdx.x * 64, bn = blockIdx.y * 64;
    int tx = threadIdx.x & 15, ty = threadIdx.x >> 4;
    ull acc[4][2] = {{0ull,0ull},{0ull,0ull},{0ull,0ull},{0ull,0ull}};
    for (int k0 = 0; k0 < K; k0 += 16){
        #pragma unroll
        for (int j=0;j<4;j++){
            int i = threadIdx.x + j*256;
            int m = i >> 4, k = i & 15;
            int gm = bm + m;
            As[k][m] = (gm < M) ? A[(size_t)gm*K + k0 + k] : 0.f;
            int gn = bn + m;
            Ws[k][m] = (gn < N) ? W[(size_t)gn*K + k0 + k] : 0.f;
        }
        __syncthreads();
        #pragma unroll
        for (int k=0;k<16;k++){
            float4 a4 = *(const float4*)&As[k][ty*4];
            ulonglong2 w2 = *(const ulonglong2*)&Ws[k][tx*4];
            ull a;
            a = pack2(a4.x); fma2(acc[0][0],a,w2.x); fma2(acc[0][1],a,w2.y);
            a = pack2(a4.y); fma2(acc[1][0],a,w2.x); fma2(acc[1][1],a,w2.y);
            a = pack2(a4.z); fma2(acc[2][0],a,w2.x); fma2(acc[2][1],a,w2.y);
            a = pack2(a4.w); fma2(acc[3][0],a,w2.x); fma2(acc[3][1],a,w2.y);
        }
        __syncthreads();
    }
    #pragma unroll
    for (int i=0;i<4;i++){
        int m = bm + ty*4 + i;
        if (m >= M) continue;
        #pragma unroll
        for (int jp=0;jp<2;jp++){
            float2 v = unpack2(acc[i][jp]);
            int n = bn + tx*4 + jp*2;
            if (n < N){   float r = v.x + (bias?bias[n]:0.f);   if(act) r=tanhf(r); C[(size_t)m*N+n]   = r; }
            if (n+1 < N){ float r = v.y + (bias?bias[n+1]:0.f); if(act) r=tanhf(r); C[(size_t)m*N+n+1] = r; }
        }
    }
}

// ---------------- persistent decoder loop ----------------
__device__ __forceinline__ void gsync(){
    __syncthreads();
    if (threadIdx.x == 0){
        __threadfence();
        unsigned gen = atomicAdd(&g_gen, 0u);
        unsigned arr = atomicAdd(&g_cnt, 1u);
        if (arr == GRID-1){
            atomicExch(&g_cnt, 0u);
            __threadfence();
            atomicAdd(&g_gen, 1u);
        } else {
            while (atomicAdd(&g_gen, 0u) == gen) { }
        }
        __threadfence();
    }
    __syncthreads();
}

// MMA sub-tile: C[32, 256] over K-slice [K0, K0+512), A in smem, W rows from L2.
__device__ __forceinline__ void mma_tile(const __nv_bfloat16* __restrict__ W, int K,
                                         int n0, int K0,
                                         const __nv_bfloat16 A_s[32][520],
                                         float* __restrict__ dst, int tid)
{
    int w = tid>>5, l = tid&31, gid = l>>2, tg = l&3;
    float acc[2][4][4];
    #pragma unroll
    for (int i=0;i<2;i++)
        #pragma unroll
        for (int j=0;j<4;j++)
            #pragma unroll
            for (int q=0;q<4;q++) acc[i][j][q] = 0.f;

    const __nv_bfloat16* wb[4];
    #pragma unroll
    for (int nt=0; nt<4; nt++)
        wb[nt] = W + (size_t)(n0 + w*32 + nt*8 + gid)*K + K0 + 2*tg;
    const __nv_bfloat16* ar0 = &A_s[gid][2*tg];
    const __nv_bfloat16* ar1 = &A_s[gid+8][2*tg];
    const __nv_bfloat16* ar2 = &A_s[gid+16][2*tg];
    const __nv_bfloat16* ar3 = &A_s[gid+24][2*tg];

    for (int kk = 0; kk < 512; kk += 16){
        u32 a[2][4];
        a[0][0] = *(const u32*)(ar0+kk);   a[0][1] = *(const u32*)(ar1+kk);
        a[0][2] = *(const u32*)(ar0+kk+8); a[0][3] = *(const u32*)(ar1+kk+8);
        a[1][0] = *(const u32*)(ar2+kk);   a[1][1] = *(const u32*)(ar3+kk);
        a[1][2] = *(const u32*)(ar2+kk+8); a[1][3] = *(const u32*)(ar3+kk+8);
        #pragma unroll
        for (int nt=0; nt<4; nt++){
            u32 bf[2];
            bf[0] = *(const u32*)(wb[nt]+kk);
            bf[1] = *(const u32*)(wb[nt]+kk+8);
            mma_bf16(acc[0][nt], a[0], bf);
            mma_bf16(acc[1][nt], a[1], bf);
        }
    }
    #pragma unroll
    for (int mt=0; mt<2; mt++){
        #pragma unroll
        for (int nt=0; nt<4; nt++){
            int row = mt*16 + gid;
            int col = n0 + w*32 + nt*8 + 2*tg;
            *(float2*)&dst[(size_t)row*4096 + col]     = make_float2(acc[mt][nt][0], acc[mt][nt][1]);
            *(float2*)&dst[(size_t)(row+8)*4096 + col] = make_float2(acc[mt][nt][2], acc[mt][nt][3]);
        }
    }
}

__global__ void __launch_bounds__(256, 1)
decoder_loop(const float* __restrict__ hs, const int* __restrict__ hlens,
             const int* __restrict__ ys, const float* __restrict__ embed,
             const float* __restrict__ Wdec,
             const float* __restrict__ bih0, const float* __restrict__ bhh0,
             const float* __restrict__ bih1, const float* __restrict__ bhh1)
{
    __shared__ __align__(16) float z_s[DUN];
    __shared__ __align__(16) float dec_s[ATTD];
    __shared__ __align__(16) float w_s[TSEQ];
    __shared__ float red_s[12];
    __shared__ __align__(16) float4 pvec[256];
    __shared__ __align__(16) __nv_bfloat16 A_s[32][520];
    __shared__ int tok_s[32];

    int cta = blockIdx.x, tid = threadIdx.x;
    int warp = tid >> 5, lane = tid & 31;

    for (int t = 0; t <= LP1; t++){
        // ---------- phase A : scores ----------
        if (t < LP1 && cta < 128){
            int b = cta >> 2, tc = cta & 3;
            ((float4*)z_s)[tid] = ((const float4*)(g_z0 + b*DUN))[tid];
            __syncthreads();
            for (int a = warp; a < ATTD; a += 8){
                const float* wr = Wdec + (size_t)a*DUN;
                ull acc = 0ull;
                #pragma unroll
                for (int i=0;i<16;i++){
                    int k = (lane<<1) + (i<<6);
                    fma2(acc, *(const ull*)(wr + k), *(const ull*)(z_s + k));
                }
                float2 p = unpack2(acc);
                float v = p.x + p.y;
                #pragma unroll
                for (int o=16;o;o>>=1) v += __shfl_xor_sync(0xffffffffu, v, o);
                if (lane==0) dec_s[a] = tanhf(v);
            }
            __syncthreads();
            int tl = tid >> 1, half = tid & 1;
            int tt = tc*128 + tl;
            const float* pr = g_pre_enc + ((size_t)(b*TSEQ) + tt)*ATTD + half*160;
            const float* dp = dec_s + half*160;
            ull a0 = 0ull, a1 = 0ull;
            #pragma unroll
            for (int i=0;i<80;i+=2){
                fma2(a0, *(const ull*)(pr + 2*i),     *(const ull*)(dp + 2*i));
                fma2(a1, *(const ull*)(pr + 2*i + 2), *(const ull*)(dp + 2*i + 2));
            }
            float2 pa = unpack2(a0), pb = unpack2(a1);
            float v = (pa.x + pa.y) + (pb.x + pb.y);
            v += __shfl_xor_sync(0xffffffffu, v, 1);
            if (half == 0){
                int hlen = hlens[b];
                g_e[b*TSEQ + tt] = (tt < hlen) ? 2.0f*v : -1e30f;
            }
        }
        gsync();

        // ---------- phase B : attc (32 CTAs) + gates L1 (64 CTAs) ----------
        if (t < LP1 && cta < 32){
            int b = cta;
            float e0 = g_e[b*TSEQ + tid];
            float e1 = g_e[b*TSEQ + 256 + tid];
            float lm = fmaxf(e0, e1);
            #pragma unroll
            for (int o=16;o;o>>=1) lm = fmaxf(lm, __shfl_xor_sync(0xffffffffu, lm, o));
            if (lane==0) red_s[warp] = lm;
            __syncthreads();
            if (tid==0){ float mm=red_s[0]; for (int w2=1;w2<8;w2++) mm=fmaxf(mm,red_s[w2]); red_s[8]=mm; }
            __syncthreads();
            float m = red_s[8];
            float p0 = expf(e0 - m), p1 = expf(e1 - m);
            w_s[tid] = p0; w_s[tid+256] = p1;
            float ps = p0 + p1;
            #pragma unroll
            for (int o=16;o;o>>=1) ps += __shfl_xor_sync(0xffffffffu, ps, o);
            if (lane==0) red_s[warp] = ps;
            __syncthreads();
            if (tid==0){ float s=0.f; for (int w2=0;w2<8;w2++) s+=red_s[w2]; red_s[9]=1.0f/s; }
            __syncthreads();
            float inv = red_s[9];
            int hlen = hlens[b];
            int d4 = tid & 127, tp = tid >> 7;
            const float4* hb = (const float4*)hs + ((size_t)(b*TSEQ))*128 + d4;
            float4 acc = make_float4(0.f,0.f,0.f,0.f);
            for (int tt = tp; tt < hlen; tt += 2){
                float wv = w_s[tt];
                float4 h4 = hb[(size_t)tt*128];
                acc.x += wv*h4.x; acc.y += wv*h4.y; acc.z += wv*h4.z; acc.w += wv*h4.w;
            }
            pvec[tid] = acc;
            __syncthreads();
            if (tp == 0){
                float4 r = pvec[d4], q = pvec[128 + d4];
                r.x = (r.x + q.x)*inv; r.y = (r.y + q.y)*inv;
                r.z = (r.z + q.z)*inv; r.w = (r.w + q.w)*inv;
                ((float4*)(g_attc + b*EPROJ))[d4] = r;
            }
        } else if (t >= 1 && cta >= 32 && cta < 96){
            int idx = cta - 32;
            int tile = idx >> 2, sp = idx & 3;
            int n0 = tile*256, K0 = sp*512;
            for (int i = tid; i < 32*512; i += 256){
                int mm = i >> 9, k = i & 511;
                int kg = K0 + k;
                float v = (kg < DUN) ? g_z0[mm*DUN + kg] : g_z1[mm*DUN + (kg-DUN)];
                A_s[mm][k] = __float2bfloat16(v);
            }
            __syncthreads();
            mma_tile(g_W1, 2048, n0, K0, A_s, g_part1 + (size_t)sp*BB*4096, tid);
        }
        gsync();

        // ---------- phase C : gates L0 (80 CTAs) + cell L1 (64 CTAs) ----------
        if (t < LP1 && cta < 80){
            int tile = cta / 5, sp = cta % 5;
            int n0 = tile*256, K0 = sp*512;
            if (tid < 32) tok_s[tid] = (t==0) ? SOSEOS : ys[tid*LLEN + (t-1)];
            __syncthreads();
            for (int i = tid; i < 32*512; i += 256){
                int mm = i >> 9, k = i & 511;
                int kg = K0 + k;
                float v;
                if (kg < 1024)      v = embed[(size_t)tok_s[mm]*DUN + kg];
                else if (kg < 1536) v = g_attc[mm*EPROJ + (kg-1024)];
                else                v = g_z0[mm*DUN + (kg-1536)];
                A_s[mm][k] = __float2bfloat16(v);
            }
            __syncthreads();
            mma_tile(g_W0, 2560, n0, K0, A_s, g_part0 + (size_t)sp*BB*4096, tid);
        } else if (t >= 1 && cta >= 80 && cta < 144){
            int e0i = ((cta-80)*256 + tid)*2;      // even, 0..32766
            int b = e0i >> 10, j = e0i & 1023;
            float2 gi = make_float2(bih1[j]   + bhh1[j],   bih1[j+1]   + bhh1[j+1]);
            float2 gf = make_float2(bih1[1024+j]+bhh1[1024+j], bih1[1025+j]+bhh1[1025+j]);
            float2 gg = make_float2(bih1[2048+j]+bhh1[2048+j], bih1[2049+j]+bhh1[2049+j]);
            float2 go = make_float2(bih1[3072+j]+bhh1[3072+j], bih1[3073+j]+bhh1[3073+j]);
            #pragma unroll
            for (int s = 0; s < NSP1; s++){
                const float* p = g_part1 + (size_t)s*BB*4096 + (size_t)b*4096 + j;
                float2 v;
                v = *(const float2*)(p);        gi.x += v.x; gi.y += v.y;
                v = *(const float2*)(p+1024);   gf.x += v.x; gf.y += v.y;
                v = *(const float2*)(p+2048);   gg.x += v.x; gg.y += v.y;
                v = *(const float2*)(p+3072);   go.x += v.x; go.y += v.y;
            }
            float cn0 = sigmoidf_(gf.x)*g_c1[e0i]   + sigmoidf_(gi.x)*tanhf(gg.x);
            float cn1 = sigmoidf_(gf.y)*g_c1[e0i+1] + sigmoidf_(gi.y)*tanhf(gg.y);
            float zn0 = sigmoidf_(go.x)*tanhf(cn0);
            float zn1 = sigmoidf_(go.y)*tanhf(cn1);
            g_c1[e0i] = cn0; g_c1[e0i+1] = cn1;
            g_z1[e0i] = zn0; g_z1[e0i+1] = zn1;
            size_t zr = ((size_t)b*LP1 + (t-1))*DUN + j;
            g_zsb[zr]   = __float2bfloat16(zn0);
            g_zsb[zr+1] = __float2bfloat16(zn1);
        }
        gsync();

        // ---------- phase D : cell L0 (128 CTAs) ----------
        if (t < LP1 && cta < 128){
            int idx = cta*256 + tid;               // 0..32767
            int b = idx >> 10, j = idx & 1023;
            float gi = bih0[j]      + bhh0[j];
            float gf = bih0[1024+j] + bhh0[1024+j];
            float gg = bih0[2048+j] + bhh0[2048+j];
            float go = bih0[3072+j] + bhh0[3072+j];
            #pragma unroll
            for (int s = 0; s < NSP0; s++){
                const float* p = g_part0 + (size_t)s*BB*4096 + (size_t)b*4096 + j;
                gi += p[0]; gf += p[1024]; gg += p[2048]; go += p[3072];
            }
            float cn = sigmoidf_(gf)*g_c0[idx] + sigmoidf_(gi)*tanhf(gg);
            float zn = sigmoidf_(go)*tanhf(cn);
            g_c0[idx] = cn; g_z0[idx] = zn;
        }
        gsync();
    }
}

// ---------------- bf16 MMA logits: C[4128,10000] = zsb @ Wo^T + bout ----------------
__global__ void logits_mma(const __nv_bfloat16* __restrict__ A, const __nv_bfloat16* __restrict__ Wo,
                           const float* __restrict__ bias, float* __restrict__ Cout)
{
    int bm = blockIdx.x*128, bn = blockIdx.y*128;
    int tid = threadIdx.x, w = tid >> 5, l = tid & 31, gid = l >> 2, tg = l & 3;
    int moff = (w & 3) * 32, noff = (w >> 2) * 64;

    float acc[2][8][4];
    #pragma unroll
    for (int i=0;i<2;i++)
        #pragma unroll
        for (int j=0;j<8;j++)
            #pragma unroll
            for (int q=0;q<4;q++) acc[i][j][q]=0.f;

    int mr[2][2];
    #pragma unroll
    for (int mt=0; mt<2; mt++){
        int r0 = bm + moff + mt*16 + gid, r1 = r0 + 8;
        mr[mt][0] = (r0 < NROWS) ? r0 : (NROWS-1);
        mr[mt][1] = (r1 < NROWS) ? r1 : (NROWS-1);
    }
    int nr[8];
    #pragma unroll
    for (int nt=0; nt<8; nt++){
        int n = bn + noff + nt*8 + gid;
        nr[nt] = (n < ODIMC) ? n : (ODIMC-1);
    }

    for (int kk = 0; kk < DUN; kk += 16){
        u32 a[2][4];
        #pragma unroll
        for (int mt=0; mt<2; mt++){
            const __nv_bfloat16* p0 = A + (size_t)mr[mt][0]*DUN + kk + 2*tg;
            const __nv_bfloat16* p1 = A + (size_t)mr[mt][1]*DUN + kk + 2*tg;
            a[mt][0] = *(const u32*)p0;
            a[mt][1] = *(const u32*)p1;
            a[mt][2] = *(const u32*)(p0 + 8);
            a[mt][3] = *(const u32*)(p1 + 8);
        }
        #pragma unroll
        for (int nt=0; nt<8; nt++){
            const __nv_bfloat16* wp = Wo + (size_t)nr[nt]*DUN + kk + 2*tg;
            u32 bf[2];
            bf[0] = *(const u32*)wp;
            bf[1] = *(const u32*)(wp + 8);
            mma_bf16(acc[0][nt], a[0], bf);
            mma_bf16(acc[1][nt], a[1], bf);
        }
    }

    #pragma unroll
    for (int mt=0; mt<2; mt++){
        #pragma unroll
        for (int nt=0; nt<8; nt++){
            int row0 = bm + moff + mt*16 + gid;
            int col  = bn + noff + nt*8 + 2*tg;
            if (col < ODIMC){
                float b0 = bias[col], b1 = bias[col+1];
                if (row0 < NROWS){
                    float2 v = make_float2(acc[mt][nt][0] + b0, acc[mt][nt][1] + b1);
                    *(float2*)&Cout[(size_t)row0*ODIMC + col] = v;
                }
                if (row0 + 8 < NROWS){
                    float2 v = make_float2(acc[mt][nt][2] + b0, acc[mt][nt][3] + b1);
                    *(float2*)&Cout[(size_t)(row0+8)*ODIMC + col] = v;
                }
            }
        }
    }
}

// ---------------- per-row logsumexp / argmax / nll ----------------
__global__ void rowloss(const float* __restrict__ logits, const int* __restrict__ ys,
                        float* __restrict__ rownll, int* __restrict__ rowhit)
{
    int r = blockIdx.x, tid = threadIdx.x;
    const float* row = logits + (size_t)r*ODIMC;
    __shared__ float sv[256]; __shared__ int si[256]; __shared__ double sd[256];
    float vmax = -INFINITY; int vidx = ODIMC;
    for (int i=tid;i<ODIMC;i+=256){ float v=row[i]; if (v>vmax){ vmax=v; vidx=i; } }
    sv[tid]=vmax; si[tid]=vidx; __syncthreads();
    for (int s=128;s;s>>=1){
        if (tid<s){
            float v2=sv[tid+s]; int i2=si[tid+s];
            if (v2>sv[tid] || (v2==sv[tid] && i2<si[tid])){ sv[tid]=v2; si[tid]=i2; }
        }
        __syncthreads();
    }
    float m = sv[0]; int amax = si[0];
    double ps = 0.0;
    for (int i=tid;i<ODIMC;i+=256) ps += (double)expf(row[i]-m);
    sd[tid]=ps; __syncthreads();
    for (int s=128;s;s>>=1){ if (tid<s) sd[tid]+=sd[tid+s]; __syncthreads(); }
    if (tid==0){
        int b = r / LP1, ll = r % LP1;
        int tgt = (ll < LLEN) ? ys[b*LLEN + ll] : SOSEOS;
        double lse = (double)m + log(sd[0]);
        rownll[r] = (float)(lse - (double)row[tgt]);
        rowhit[r] = (amax == tgt) ? 1 : 0;
    }
}

__global__ void finalize(const float* __restrict__ rownll, const int* __restrict__ rowhit,
                         float* __restrict__ out, int out_size)
{
    __shared__ double sd[256]; __shared__ int sh[256];
    int tid = threadIdx.x;
    double s = 0.0; int h = 0;
    for (int i=tid;i<NROWS;i+=256){ s += (double)rownll[i]; h += rowhit[i]; }
    sd[tid]=s; sh[tid]=h; __syncthreads();
    for (int st=128;st;st>>=1){ if (tid<st){ sd[tid]+=sd[tid+st]; sh[tid]+=sh[tid+st]; } __syncthreads(); }
    if (tid==0){
        double loss = sd[0]/(double)NROWS * (double)LLEN;
        double acc  = (double)sh[0]/(double)NROWS;
        double ppl  = exp(loss/(double)BB);
        if (out_size>0) out[0]=(float)loss;
        if (out_size>1) out[1]=(float)acc;
        if (out_size>2) out[2]=(float)ppl;
    }
    for (int i=3+tid;i<out_size;i+=256) out[i]=0.f;
}

// ---------------- launcher ----------------
static void* symaddr(const void* sym){ void* p=nullptr; cudaGetSymbolAddress(&p, sym); return p; }

extern "C" void kernel_launch(void* const* d_in, const int* in_sizes, int n_in,
                              void* d_out, int out_size)
{
    const float* hs    = (const float*)d_in[0];
    const int*   hlens = (const int*)  d_in[1];
    const int*   ys    = (const int*)  d_in[2];
    const float* embed = (const float*)d_in[3];
    const float* Wenc  = (const float*)d_in[4];
    const float* benc  = (const float*)d_in[5];
    const float* Wdec  = (const float*)d_in[6];
    const float* Wih0  = (const float*)d_in[7];
    const float* Whh0  = (const float*)d_in[8];
    const float* bih0  = (const float*)d_in[9];
    const float* bhh0  = (const float*)d_in[10];
    const float* Wih1  = (const float*)d_in[11];
    const float* Whh1  = (const float*)d_in[12];
    const float* bih1  = (const float*)d_in[13];
    const float* bhh1  = (const float*)d_in[14];
    const float* Wout  = (const float*)d_in[15];
    const float* bout  = (const float*)d_in[16];
    float* out = (float*)d_out;

    float* pre_enc = (float*)symaddr(g_pre_enc);
    __nv_bfloat16* zsb = (__nv_bfloat16*)symaddr(g_zsb);
    __nv_bfloat16* W0b = (__nv_bfloat16*)symaddr(g_W0);
    __nv_bfloat16* W1b = (__nv_bfloat16*)symaddr(g_W1);
    __nv_bfloat16* Wob = (__nv_bfloat16*)symaddr(g_Wo);
    float* logits  = (float*)symaddr(g_logits);
    float* rownll  = (float*)symaddr(g_rownll);
    int*   rowhit  = (int*)  symaddr(g_rowhit);

    init_all<<<128,256>>>();

    convcat<<<1024,256>>>(Wih0, Whh0, W0b, 4096, 1536, 1024);
    convcat<<<1024,256>>>(Wih1, Whh1, W1b, 4096, 1024, 1024);
    convcat<<<1024,256>>>(Wout, Wout, Wob, ODIMC, 1024, 0);

    // pre_enc = tanh(hs @ Wenc^T + benc):  [16384,320]
    sgemm_nt<<<dim3(256,5),256>>>(hs, Wenc, benc, pre_enc, BB*TSEQ, ATTD, EPROJ, 1);

    // entire recurrence in one persistent kernel
    decoder_loop<<<GRID,256>>>(hs, hlens, ys, embed, Wdec, bih0, bhh0, bih1, bhh1);

    // logits = zsb @ Wo^T + bout
    logits_mma<<<dim3(33,79),256>>>(zsb, Wob, bout, logits);

    rowloss<<<NROWS,256>>>(logits, ys, rownll, rowhit);
    finalize<<<1,256>>>(rownll, rowhit, out, out_size);
}